// round 13
// baseline (speedup 1.0000x reference)
#include <cuda_runtime.h>
#include <math.h>

// InfoNCE loss: B=131072 rows, D=512 fp32.
// loss = mean_i log(1 + exp((neg_i - pos_i)/T))
// 768 MB streamed once. Pinned at LTS byte ceiling (~7.1 TB/s) in all
// one-shot configs; this version is a single-wave PERSISTENT kernel with a
// per-warp DOUBLE-BUFFERED row pipeline: row i+1's 12 LDG.128 issue before
// row i's reduction, sustaining MLP~12 with no per-row load drain and no
// wave transitions. 296 CTAs (2/SM at <=128 regs), ~55 rows/warp.
// Single-node graph (threadfence reduction, no memset).

#define D 512
#define TEMPERATURE 1.5f

__device__ float        g_partial = 0.0f;
__device__ unsigned int g_count   = 0u;

__device__ __forceinline__ float4 ldg_nc_prefetch(const float4* ptr) {
    float4 v;
    asm volatile("ld.global.nc.L2::256B.v4.f32 {%0,%1,%2,%3}, [%4];"
                 : "=f"(v.x), "=f"(v.y), "=f"(v.z), "=f"(v.w)
                 : "l"(ptr));
    return v;
}

// Issue all 12 row loads (a,p,n) into buf[0..11].
__device__ __forceinline__ void load_row(const float* __restrict__ a,
                                         const float* __restrict__ p,
                                         const float* __restrict__ n,
                                         int row, int lane, float4* buf)
{
    const size_t off = (size_t)row * D;
    const float4* __restrict__ a4 = (const float4*)(a + off);
    const float4* __restrict__ p4 = (const float4*)(p + off);
    const float4* __restrict__ n4 = (const float4*)(n + off);
    #pragma unroll
    for (int k = 0; k < 4; ++k) buf[k]     = ldg_nc_prefetch(&a4[lane + 32 * k]);
    #pragma unroll
    for (int k = 0; k < 4; ++k) buf[4 + k] = ldg_nc_prefetch(&p4[lane + 32 * k]);
    #pragma unroll
    for (int k = 0; k < 4; ++k) buf[8 + k] = ldg_nc_prefetch(&n4[lane + 32 * k]);
}

// Reduce one buffered row; lane 0 returns its loss contribution, others 0.
__device__ __forceinline__ float row_loss(const float4* buf, int lane, float invB)
{
    float aa = 0.f, pp = 0.f, nn = 0.f, ap = 0.f, an = 0.f;
    #pragma unroll
    for (int k = 0; k < 4; ++k) {
        const float4 va = buf[k], vp = buf[4 + k], vn = buf[8 + k];
        aa = fmaf(va.x, va.x, fmaf(va.y, va.y, fmaf(va.z, va.z, fmaf(va.w, va.w, aa))));
        pp = fmaf(vp.x, vp.x, fmaf(vp.y, vp.y, fmaf(vp.z, vp.z, fmaf(vp.w, vp.w, pp))));
        nn = fmaf(vn.x, vn.x, fmaf(vn.y, vn.y, fmaf(vn.z, vn.z, fmaf(vn.w, vn.w, nn))));
        ap = fmaf(va.x, vp.x, fmaf(va.y, vp.y, fmaf(va.z, vp.z, fmaf(va.w, vp.w, ap))));
        an = fmaf(va.x, vn.x, fmaf(va.y, vn.y, fmaf(va.z, vn.z, fmaf(va.w, vn.w, an))));
    }
    #pragma unroll
    for (int off = 16; off > 0; off >>= 1) {
        aa += __shfl_xor_sync(0xFFFFFFFFu, aa, off);
        pp += __shfl_xor_sync(0xFFFFFFFFu, pp, off);
        nn += __shfl_xor_sync(0xFFFFFFFFu, nn, off);
        ap += __shfl_xor_sync(0xFFFFFFFFu, ap, off);
        an += __shfl_xor_sync(0xFFFFFFFFu, an, off);
    }
    float r = 0.f;
    if (lane == 0) {
        const float na  = fmaxf(sqrtf(aa), 1e-12f);
        const float npo = fmaxf(sqrtf(pp), 1e-12f);
        const float nne = fmaxf(sqrtf(nn), 1e-12f);
        const float pos = ap / (na * npo);
        const float neg = an / (na * nne);
        const float z = (neg - pos) * (1.0f / TEMPERATURE);
        r = log1pf(expf(z)) * invB;  // z in [-1.34,1.34], no overflow
    }
    return r;
}

__global__ void __launch_bounds__(256, 2)
infonce_kernel(const float* __restrict__ a,
               const float* __restrict__ p,
               const float* __restrict__ n,
               float* __restrict__ out,
               int B, float invB)
{
    const int lane = threadIdx.x & 31;
    const int warp_id = (int)((blockIdx.x * (unsigned)blockDim.x + threadIdx.x) >> 5);
    const int stride  = (int)((gridDim.x * blockDim.x) >> 5);

    float4 bufA[12], bufB[12];
    float acc = 0.f;

    int row = warp_id;
    if (row < B) {
        load_row(a, p, n, row, lane, bufA);   // prologue: fill A
        // Ping-pong: load next row into the other buffer, then reduce current.
        while (true) {
            int nrow = row + stride;
            if (nrow < B) {
                load_row(a, p, n, nrow, lane, bufB);
                acc += row_loss(bufA, lane, invB);
                row = nrow;
            } else {
                acc += row_loss(bufA, lane, invB);
                break;
            }
            nrow = row + stride;
            if (nrow < B) {
                load_row(a, p, n, nrow, lane, bufA);
                acc += row_loss(bufB, lane, invB);
                row = nrow;
            } else {
                acc += row_loss(bufB, lane, invB);
                break;
            }
        }
    }

    // Block reduction (8 warps), then threadfence-reduction across blocks.
    __shared__ float s[8];
    __shared__ bool  is_last;
    const int wid = threadIdx.x >> 5;
    if (lane == 0) s[wid] = acc;
    __syncthreads();
    if (threadIdx.x == 0) {
        float sum = s[0];
        #pragma unroll
        for (int i = 1; i < 8; ++i) sum += s[i];
        atomicAdd(&g_partial, sum);
        __threadfence();
        unsigned int prev = atomicAdd(&g_count, 1u);
        is_last = (prev == gridDim.x - 1u);
        if (is_last) {
            *out = g_partial;
            g_partial = 0.0f;
            g_count   = 0u;
        }
    }
}

extern "C" void kernel_launch(void* const* d_in, const int* in_sizes, int n_in,
                              void* d_out, int out_size)
{
    const float* anchors   = (const float*)d_in[0];
    const float* positives = (const float*)d_in[1];
    const float* negatives = (const float*)d_in[2];
    float* out = (float*)d_out;

    const int B = in_sizes[0] / D;

    const int threads = 256;           // 8 warps per CTA
    const int blocks  = 148 * 2;       // single wave at 2 CTAs/SM (128 regs)
    infonce_kernel<<<blocks, threads>>>(anchors, positives, negatives, out,
                                        B, 1.0f / (float)B);
}

// round 14
// speedup vs baseline: 1.0178x; 1.0178x over previous
#include <cuda_runtime.h>
#include <math.h>

// InfoNCE loss: B=131072 rows, D=512 fp32.
// loss = mean_i log(1 + exp((neg_i - pos_i)/T))
// 768 MB streamed once -> pinned at the LTS/HBM byte ceiling (~7.1 TB/s,
// confirmed across occ 24/44/71/96%, load width 128/256, persistent +
// double-buffered pipelining, cache policies, graph node counts).
// Terminal config (best measured sample, 113.1us): one warp per row, CTA per
// 8 rows, 12x LDG.128 front-batched via ld.global.nc + L2::256B prefetch,
// occ cap 4, single-node graph (threadfence reduction, no memset node).

#define D 512
#define TEMPERATURE 1.5f

__device__ float        g_partial = 0.0f;
__device__ unsigned int g_count   = 0u;

__device__ __forceinline__ float4 ldg_nc_prefetch(const float4* ptr) {
    float4 v;
    asm volatile("ld.global.nc.L2::256B.v4.f32 {%0,%1,%2,%3}, [%4];"
                 : "=f"(v.x), "=f"(v.y), "=f"(v.z), "=f"(v.w)
                 : "l"(ptr));
    return v;
}

__global__ void __launch_bounds__(256, 4)
infonce_kernel(const float* __restrict__ a,
               const float* __restrict__ p,
               const float* __restrict__ n,
               float* __restrict__ out,
               int B, float invB)
{
    const int warp_global = (int)((blockIdx.x * (unsigned)blockDim.x + threadIdx.x) >> 5);
    const int lane = threadIdx.x & 31;

    float aa = 0.f, pp = 0.f, nn = 0.f, ap = 0.f, an = 0.f;

    if (warp_global < B) {
        const size_t row_off = (size_t)warp_global * D;
        const float4* __restrict__ a4 = (const float4*)(a + row_off);
        const float4* __restrict__ p4 = (const float4*)(p + row_off);
        const float4* __restrict__ n4 = (const float4*)(n + row_off);

        // Batch ALL 12 float4 loads up front (48 data regs, ~56 total),
        // each with an L2 256B prefetch hint.
        float4 va[4], vp[4], vn[4];
        #pragma unroll
        for (int k = 0; k < 4; ++k) va[k] = ldg_nc_prefetch(&a4[lane + 32 * k]);
        #pragma unroll
        for (int k = 0; k < 4; ++k) vp[k] = ldg_nc_prefetch(&p4[lane + 32 * k]);
        #pragma unroll
        for (int k = 0; k < 4; ++k) vn[k] = ldg_nc_prefetch(&n4[lane + 32 * k]);

        #pragma unroll
        for (int k = 0; k < 4; ++k) {
            aa = fmaf(va[k].x, va[k].x, fmaf(va[k].y, va[k].y, fmaf(va[k].z, va[k].z, fmaf(va[k].w, va[k].w, aa))));
            pp = fmaf(vp[k].x, vp[k].x, fmaf(vp[k].y, vp[k].y, fmaf(vp[k].z, vp[k].z, fmaf(vp[k].w, vp[k].w, pp))));
            nn = fmaf(vn[k].x, vn[k].x, fmaf(vn[k].y, vn[k].y, fmaf(vn[k].z, vn[k].z, fmaf(vn[k].w, vn[k].w, nn))));
            ap = fmaf(va[k].x, vp[k].x, fmaf(va[k].y, vp[k].y, fmaf(va[k].z, vp[k].z, fmaf(va[k].w, vp[k].w, ap))));
            an = fmaf(va[k].x, vn[k].x, fmaf(va[k].y, vn[k].y, fmaf(va[k].z, vn[k].z, fmaf(va[k].w, vn[k].w, an))));
        }
    }

    // Warp tree-reduction of the 5 partial sums.
    #pragma unroll
    for (int off = 16; off > 0; off >>= 1) {
        aa += __shfl_xor_sync(0xFFFFFFFFu, aa, off);
        pp += __shfl_xor_sync(0xFFFFFFFFu, pp, off);
        nn += __shfl_xor_sync(0xFFFFFFFFu, nn, off);
        ap += __shfl_xor_sync(0xFFFFFFFFu, ap, off);
        an += __shfl_xor_sync(0xFFFFFFFFu, an, off);
    }

    float partial = 0.f;
    if (lane == 0 && warp_global < B) {
        const float na  = fmaxf(sqrtf(aa), 1e-12f);
        const float npo = fmaxf(sqrtf(pp), 1e-12f);
        const float nne = fmaxf(sqrtf(nn), 1e-12f);
        const float pos = ap / (na * npo);
        const float neg = an / (na * nne);
        const float z = (neg - pos) * (1.0f / TEMPERATURE);
        // -log_softmax[0] = log(1 + exp(z)); z in [-1.34, 1.34] -> no overflow
        partial = log1pf(expf(z)) * invB;
    }

    // Block reduction (8 warps), then threadfence-reduction across blocks.
    __shared__ float s[8];
    const int wid = threadIdx.x >> 5;
    if (lane == 0) s[wid] = partial;
    __syncthreads();
    if (threadIdx.x == 0) {
        float sum = s[0];
        #pragma unroll
        for (int i = 1; i < 8; ++i) sum += s[i];
        atomicAdd(&g_partial, sum);
        __threadfence();
        unsigned int prev = atomicAdd(&g_count, 1u);
        if (prev == gridDim.x - 1u) {
            // All other blocks' adds are visible (their fences precede their
            // counter increments). Publish and reset for the next replay.
            *out = g_partial;
            g_partial = 0.0f;
            g_count   = 0u;
        }
    }
}

extern "C" void kernel_launch(void* const* d_in, const int* in_sizes, int n_in,
                              void* d_out, int out_size)
{
    const float* anchors   = (const float*)d_in[0];
    const float* positives = (const float*)d_in[1];
    const float* negatives = (const float*)d_in[2];
    float* out = (float*)d_out;

    const int B = in_sizes[0] / D;

    const int threads = 256;               // 8 warps = 8 rows per block
    const int blocks = (B + 7) / 8;
    infonce_kernel<<<blocks, threads>>>(anchors, positives, negatives, out,
                                        B, 1.0f / (float)B);
}